// round 11
// baseline (speedup 1.0000x reference)
#include <cuda_runtime.h>
#include <cuda_bf16.h>
#include <cstdint>

#define N_NODES 50000
#define N_EDGES 600000
#define D_FEAT  128
#define OUT_DIM 128
#define K_DIM   256

#define SCAN_BLK 512
#define N_SCAN_BLKS ((N_NODES + SCAN_BLK - 1) / SCAN_BLK)   // 98

// ---------------------------------------------------------------------------
// Scratch (static device globals)
// ---------------------------------------------------------------------------
__device__ int g_cnt_i [N_NODES];
__device__ int g_off   [N_NODES];
__device__ int g_btot  [N_SCAN_BLKS];
__device__ int g_rank  [N_EDGES];    // rank of edge within its segment
__device__ int g_eid   [N_EDGES];    // edge ids sorted by destination node
__device__ __align__(16) float g_agg[N_NODES * D_FEAT];   // 25.6 MB

// ---------------------------------------------------------------------------
// Kernel 1: zero counters
// ---------------------------------------------------------------------------
__global__ void zero_counters_kernel() {
    int i = blockIdx.x * blockDim.x + threadIdx.x;
    if (i < N_NODES) g_cnt_i[i] = 0;
}

// ---------------------------------------------------------------------------
// Kernel 2: histogram + per-edge rank in ONE atomic pass
// ---------------------------------------------------------------------------
__global__ void count_rank_kernel(const int* __restrict__ src_idx) {
    int e = blockIdx.x * blockDim.x + threadIdx.x;
    if (e < N_EDGES) g_rank[e] = atomicAdd(&g_cnt_i[src_idx[e]], 1);
}

// ---------------------------------------------------------------------------
// Kernel 3: per-block exclusive scan; block totals to g_btot
// ---------------------------------------------------------------------------
__global__ __launch_bounds__(SCAN_BLK)
void scan_partial_kernel() {
    __shared__ int sh[SCAN_BLK];
    const int tid = threadIdx.x;
    const int i   = blockIdx.x * SCAN_BLK + tid;
    const int v   = (i < N_NODES) ? g_cnt_i[i] : 0;
    sh[tid] = v;
    __syncthreads();
    #pragma unroll
    for (int d = 1; d < SCAN_BLK; d <<= 1) {
        int t = (tid >= d) ? sh[tid - d] : 0;
        __syncthreads();
        sh[tid] += t;
        __syncthreads();
    }
    if (i < N_NODES) g_off[i] = sh[tid] - v;
    if (tid == SCAN_BLK - 1) g_btot[blockIdx.x] = sh[tid];
}

// ---------------------------------------------------------------------------
// Inline 98-element exclusive prefix of g_btot (~200 cyc; replaces a 4.5us
// standalone kernel). All threads must join the syncs.
// ---------------------------------------------------------------------------
__device__ __forceinline__ void boff_scan(int* sb) {
    const int tid = threadIdx.x;
    int v = 0;
    if (tid < 128) {
        v = (tid < N_SCAN_BLKS) ? g_btot[tid] : 0;
        sb[tid] = v;
    }
    __syncthreads();
    #pragma unroll
    for (int d = 1; d < 128; d <<= 1) {
        int x = (tid < 128 && tid >= d) ? sb[tid - d] : 0;
        __syncthreads();
        if (tid < 128) sb[tid] += x;
        __syncthreads();
    }
    if (tid < 128) sb[tid] -= v;   // exclusive
    __syncthreads();
}

// ---------------------------------------------------------------------------
// Kernel 4: scatter edge ids — atomic-free (rank precomputed)
// ---------------------------------------------------------------------------
__global__ __launch_bounds__(256)
void scatter_ids_kernel(const int* __restrict__ src_idx) {
    __shared__ int sb[128];
    boff_scan(sb);
    int e = blockIdx.x * blockDim.x + threadIdx.x;
    if (e < N_EDGES) {
        const int s = src_idx[e];
        g_eid[g_off[s] + sb[s >> 9] + g_rank[e]] = e;
    }
}

// ---------------------------------------------------------------------------
// Kernel 5: gather-reduce. One warp per node; lane owns a float4 chunk.
// ---------------------------------------------------------------------------
__global__ __launch_bounds__(256)
void gather_kernel(const float* __restrict__ nbr_feat) {
    __shared__ int sb[128];
    boff_scan(sb);

    const int warp = (blockIdx.x * blockDim.x + threadIdx.x) >> 5;
    const int lane = threadIdx.x & 31;
    if (warp >= N_NODES) return;

    const int base = g_off[warp] + sb[warp >> 9];
    const int deg  = g_cnt_i[warp];

    const float4* nb4 = reinterpret_cast<const float4*>(nbr_feat);
    float4 acc = make_float4(0.f, 0.f, 0.f, 0.f);

    int i = 0;
    for (; i + 4 <= deg; i += 4) {
        const int e0 = g_eid[base + i];
        const int e1 = g_eid[base + i + 1];
        const int e2 = g_eid[base + i + 2];
        const int e3 = g_eid[base + i + 3];
        const float4 v0 = nb4[(size_t)e0 * (D_FEAT / 4) + lane];
        const float4 v1 = nb4[(size_t)e1 * (D_FEAT / 4) + lane];
        const float4 v2 = nb4[(size_t)e2 * (D_FEAT / 4) + lane];
        const float4 v3 = nb4[(size_t)e3 * (D_FEAT / 4) + lane];
        acc.x += (v0.x + v1.x) + (v2.x + v3.x);
        acc.y += (v0.y + v1.y) + (v2.y + v3.y);
        acc.z += (v0.z + v1.z) + (v2.z + v3.z);
        acc.w += (v0.w + v1.w) + (v2.w + v3.w);
    }
    for (; i < deg; ++i) {
        const int e = g_eid[base + i];
        const float4 v = nb4[(size_t)e * (D_FEAT / 4) + lane];
        acc.x += v.x; acc.y += v.y; acc.z += v.z; acc.w += v.w;
    }

    const float s = (deg > 0) ? (1.0f / (float)deg) : 0.0f;
    acc.x *= s; acc.y *= s; acc.z *= s; acc.w *= s;
    reinterpret_cast<float4*>(g_agg)[(size_t)warp * (D_FEAT / 4) + lane] = acc;
}

// ---------------------------------------------------------------------------
// Kernel 6: fused concat + GEMM, X stored PRE-DUPLICATED in smem so the inner
// loop has ZERO mov.b64 dup instructions:
//   per k: 2 LDS.64 (W pairs) + 8 LDS.64 (Xdup broadcast) + 16 fma.f32x2
//   = 26 issue slots / 32 FMA  (was 76/64 with register dups).
// K in quarters (KQ=64): smem = W 32KB + Xdup 32KB = 64KB.
// Phases 0,1: x=self_feat (k 0..127); phases 2,3: x=g_agg (k 128..255).
// launch_bounds (256,2) = 128-reg budget (NEVER lower: (256,4) spilled, +50us).
// ---------------------------------------------------------------------------
#define BM   64
#define TPB  256
#define KQ   64
#define GEMM_SMEM ((KQ * OUT_DIM + BM * KQ * 2) * 4)   // 32768 + 32768 = 65536

__global__ __launch_bounds__(TPB, 2)
void gemm_kernel(const float* __restrict__ self_feat,
                 const float* __restrict__ W,
                 float*       __restrict__ out) {
    extern __shared__ float sh[];
    float* Wsh = sh;                  // [KQ][OUT_DIM]        32KB
    float* Xd  = sh + KQ * OUT_DIM;   // [BM][KQ*2] dup pairs 32KB

    const int tid = threadIdx.x;
    const int n0  = blockIdx.x * BM;

    const int j0 = (tid & 31) * 4;    // output column base
    const int r0 = (tid >> 5) * 8;    // row base within tile

    unsigned long long a01[8], a23[8];
    #pragma unroll
    for (int r = 0; r < 8; ++r) { a01[r] = 0ull; a23[r] = 0ull; }

    #pragma unroll
    for (int phase = 0; phase < 4; ++phase) {
        const float* xsrc = (phase < 2) ? self_feat : g_agg;
        const int    kofs = (phase & 1) * KQ;   // k offset within the 128-half

        if (phase) __syncthreads();

        // W quarter: rows [phase*KQ, phase*KQ+64) of W[256][128] -> 2048 float4
        {
            const float4* W4 = reinterpret_cast<const float4*>(W + phase * KQ * OUT_DIM);
            float4* Wsh4 = reinterpret_cast<float4*>(Wsh);
            #pragma unroll
            for (int i = tid; i < KQ * OUT_DIM / 4; i += TPB) Wsh4[i] = W4[i];
        }
        // Xdup quarter: 64 rows x 16 float4 reads; each element stored as (x,x)
        {
            const float4* x4 = reinterpret_cast<const float4*>(xsrc);
            #pragma unroll
            for (int i = tid; i < BM * (KQ / 4); i += TPB) {
                const int r  = i >> 4;           // /(KQ/4)=16
                const int c4 = i & 15;
                const int n  = n0 + r;
                float4 v = make_float4(0.f, 0.f, 0.f, 0.f);
                if (n < N_NODES)
                    v = x4[(size_t)n * (D_FEAT / 4) + (kofs >> 2) + c4];
                float2* dst = reinterpret_cast<float2*>(&Xd[r * (KQ * 2) + c4 * 8]);
                dst[0] = make_float2(v.x, v.x);
                dst[1] = make_float2(v.y, v.y);
                dst[2] = make_float2(v.z, v.z);
                dst[3] = make_float2(v.w, v.w);
            }
        }
        __syncthreads();

        #pragma unroll 4
        for (int k = 0; k < KQ; ++k) {
            const unsigned long long wA =
                *reinterpret_cast<const unsigned long long*>(&Wsh[k * OUT_DIM + j0]);
            const unsigned long long wB =
                *reinterpret_cast<const unsigned long long*>(&Wsh[k * OUT_DIM + j0 + 2]);
            #pragma unroll
            for (int r = 0; r < 8; ++r) {
                const unsigned long long xd =
                    *reinterpret_cast<const unsigned long long*>(
                        &Xd[(r0 + r) * (KQ * 2) + k * 2]);   // broadcast, free
                asm("fma.rn.f32x2 %0, %1, %2, %0;" : "+l"(a01[r]) : "l"(xd), "l"(wA));
                asm("fma.rn.f32x2 %0, %1, %2, %0;" : "+l"(a23[r]) : "l"(xd), "l"(wB));
            }
        }
    }

    #pragma unroll
    for (int r = 0; r < 8; ++r) {
        const int n = n0 + r0 + r;
        if (n < N_NODES) {
            float o0, o1, o2, o3;
            asm("mov.b64 {%0, %1}, %2;" : "=f"(o0), "=f"(o1) : "l"(a01[r]));
            asm("mov.b64 {%0, %1}, %2;" : "=f"(o2), "=f"(o3) : "l"(a23[r]));
            *reinterpret_cast<float4*>(&out[(size_t)n * OUT_DIM + j0]) =
                make_float4(o0, o1, o2, o3);
        }
    }
}

// ---------------------------------------------------------------------------
// Launch — 6 kernels, strictly serial (overlap attempts R7-R9 all lost to
// SM-residency contention).
// ---------------------------------------------------------------------------
extern "C" void kernel_launch(void* const* d_in, const int* in_sizes, int n_in,
                              void* d_out, int out_size) {
    const float* self_feat = (const float*)d_in[0];
    const float* nbr_feat  = (const float*)d_in[1];
    const int*   src_idx   = (const int*)  d_in[2];
    const float* W         = (const float*)d_in[3];
    float*       out       = (float*)d_out;

    (void)in_sizes; (void)n_in; (void)out_size;

    const int nodes_blks = (N_NODES + 255) / 256;
    const int edges_blks = (N_EDGES + 255) / 256;

    zero_counters_kernel<<<nodes_blks, 256>>>();           // 1
    count_rank_kernel<<<edges_blks, 256>>>(src_idx);       // 2
    scan_partial_kernel<<<N_SCAN_BLKS, SCAN_BLK>>>();      // 3
    scatter_ids_kernel<<<edges_blks, 256>>>(src_idx);      // 4
    gather_kernel<<<(N_NODES + 7) / 8, 256>>>(nbr_feat);   // 5

    cudaFuncSetAttribute(gemm_kernel,
                         cudaFuncAttributeMaxDynamicSharedMemorySize, GEMM_SMEM);
    gemm_kernel<<<(N_NODES + BM - 1) / BM, TPB, GEMM_SMEM>>>(self_feat, W, out);  // 6
}